// round 11
// baseline (speedup 1.0000x reference)
#include <cuda_runtime.h>
#include <cuda_bf16.h>
#include <math.h>

// PSROIPool (R-FCN position-sensitive ROI pooling), x: (49, 1024, 1024) f32,
// region: (4,) f32 ijhw fractional. Output: scalar f32.
//
// Only ~1.6 MB of the 205 MB input is actually read (49 bins of ~89x89 px),
// so this is latency/launch-bound, not bandwidth-bound. Two tiny kernels:
//   A) 49 blocks -> per-bin spatial mean into __device__ scratch (double)
//   B) 1 warp    -> mean of 49 bin means -> d_out[0]

#define PSK 7
#define PSH 1024
#define PSW 1024

__device__ double g_bin_means[PSK * PSK];

__inline__ __device__ double warp_reduce_d(double v) {
#pragma unroll
    for (int o = 16; o > 0; o >>= 1)
        v += __shfl_down_sync(0xffffffffu, v, o);
    return v;
}

__global__ void __launch_bounds__(256)
psroi_bins_kernel(const float* __restrict__ x, const float* __restrict__ region) {
    const int b  = blockIdx.x;          // bin index 0..48
    const int bi = b / PSK;             // row-bin i
    const int bj = b % PSK;             // col-bin j

    // --- replicate reference scalar math in fp32 ---
    const float ri = region[0], rj = region[1], rh = region[2], rw = region[3];
    const float i0 = ri - rh * 0.5f, i1 = ri + rh * 0.5f;
    const float j0 = rj - rw * 0.5f, j1 = rj + rw * 0.5f;

    // bin centers: interior points m=1..K of (K+2)-point linspace, step = span/(K+1)
    const float ic = i0 + (i1 - i0) * ((float)(bi + 1) / (float)(PSK + 1));
    const float jc = j0 + (j1 - j0) * ((float)(bj + 1) / (float)(PSK + 1));
    const float bh = rh / (float)PSK;
    const float bw = rw / (float)PSK;

    int r0 = (int)floorf((ic - bh * 0.5f) * (float)PSH);
    int r1 = (int)ceilf ((ic + bh * 0.5f) * (float)PSH);
    int c0 = (int)floorf((jc - bw * 0.5f) * (float)PSW);
    int c1 = (int)ceilf ((jc + bw * 0.5f) * (float)PSW);
    r0 = max(r0, 0); r1 = min(r1, PSH);
    c0 = max(c0, 0); c1 = min(c1, PSW);

    const int nr = r1 - r0;
    const int nc = c1 - c0;
    const int total = nr * nc;          // ~7.9K pixels

    const float* __restrict__ ch = x + (size_t)b * (PSH * PSW);

    double acc = 0.0;
    // flat index -> (row, col); consecutive threads hit consecutive cols (coalesced)
    for (int p = threadIdx.x; p < total; p += blockDim.x) {
        const int r = p / nc;
        const int c = p - r * nc;
        acc += (double)__ldg(&ch[(size_t)(r0 + r) * PSW + (c0 + c)]);
    }

    // block reduce (8 warps)
    __shared__ double wsum[8];
    const int lane = threadIdx.x & 31;
    const int wid  = threadIdx.x >> 5;
    acc = warp_reduce_d(acc);
    if (lane == 0) wsum[wid] = acc;
    __syncthreads();
    if (wid == 0) {
        double v = (lane < 8) ? wsum[lane] : 0.0;
        v = warp_reduce_d(v);
        if (lane == 0)
            g_bin_means[b] = (total > 0) ? (v / (double)total) : 0.0;
    }
}

__global__ void psroi_final_kernel(float* __restrict__ out) {
    const int t = threadIdx.x;          // 32 threads, one warp
    double v = g_bin_means[t];          // t in 0..31
    if (t < PSK * PSK - 32)             // t+32 in 32..48 for t<17
        v += g_bin_means[t + 32];
    v = warp_reduce_d(v);
    if (t == 0)
        out[0] = (float)(v / (double)(PSK * PSK));
}

extern "C" void kernel_launch(void* const* d_in, const int* in_sizes, int n_in,
                              void* d_out, int out_size) {
    const float* x      = (const float*)d_in[0];  // (49, 1024, 1024) f32
    const float* region = (const float*)d_in[1];  // (4,) f32
    float* out = (float*)d_out;

    psroi_bins_kernel<<<PSK * PSK, 256>>>(x, region);
    psroi_final_kernel<<<1, 32>>>(out);
}

// round 12
// speedup vs baseline: 1.2948x; 1.2948x over previous
#include <cuda_runtime.h>
#include <cuda_bf16.h>
#include <math.h>

// PSROIPool (R-FCN), x: (49, 1024, 1024) f32, region: (4,) f32 ijhw.
// Output: scalar f32 = mean over 49 bins of per-bin spatial mean.
//
// R11 was 2 launches = ~9us of pure launch overhead (final kernel alone was
// 4.45us). Fused version: 49 blocks, last-arriving block does the final
// deterministic 49-way reduction and resets the ticket for graph replay.

#define PSK 7
#define PSH 1024
#define PSW 1024

__device__ double        g_bin_means[PSK * PSK];
__device__ unsigned int  g_ticket;     // zero-init at load; reset by last block each launch

__inline__ __device__ double warp_reduce_d(double v) {
#pragma unroll
    for (int o = 16; o > 0; o >>= 1)
        v += __shfl_down_sync(0xffffffffu, v, o);
    return v;
}

__global__ void __launch_bounds__(256)
psroi_fused_kernel(const float* __restrict__ x, const float* __restrict__ region,
                   float* __restrict__ out) {
    const int b  = blockIdx.x;          // bin 0..48
    const int bi = b / PSK;
    const int bj = b % PSK;

    // --- replicate reference scalar math in fp32 ---
    const float ri = region[0], rj = region[1], rh = region[2], rw = region[3];
    const float i0 = ri - rh * 0.5f, i1 = ri + rh * 0.5f;
    const float j0 = rj - rw * 0.5f, j1 = rj + rw * 0.5f;

    const float ic = i0 + (i1 - i0) * ((float)(bi + 1) / (float)(PSK + 1));
    const float jc = j0 + (j1 - j0) * ((float)(bj + 1) / (float)(PSK + 1));
    const float bh = rh / (float)PSK;
    const float bw = rw / (float)PSK;

    int r0 = (int)floorf((ic - bh * 0.5f) * (float)PSH);
    int r1 = (int)ceilf ((ic + bh * 0.5f) * (float)PSH);
    int c0 = (int)floorf((jc - bw * 0.5f) * (float)PSW);
    int c1 = (int)ceilf ((jc + bw * 0.5f) * (float)PSW);
    r0 = max(r0, 0); r1 = min(r1, PSH);
    c0 = max(c0, 0); c1 = min(c1, PSW);

    const int nr    = r1 - r0;
    const int nc    = c1 - c0;
    const int total = nr * nc;          // ~7.9K pixels

    const float* __restrict__ ch = x + (size_t)b * (PSH * PSW);

    // Per-thread accumulate in fp32 (short dep chain, values ~N(0,1), ~31
    // terms -> error ~1e-6, far inside the 1e-3 budget). Cross-thread
    // reduction stays in double. Unroll to front-batch the L2 loads.
    float facc = 0.0f;
#pragma unroll 4
    for (int p = threadIdx.x; p < total; p += 256) {
        const int r = p / nc;
        const int c = p - r * nc;
        facc += __ldg(&ch[(size_t)(r0 + r) * PSW + (c0 + c)]);
    }

    __shared__ double wsum[8];
    const int lane = threadIdx.x & 31;
    const int wid  = threadIdx.x >> 5;
    double acc = warp_reduce_d((double)facc);
    if (lane == 0) wsum[wid] = acc;
    __syncthreads();

    __shared__ int s_last;
    if (wid == 0) {
        double v = (lane < 8) ? wsum[lane] : 0.0;
        v = warp_reduce_d(v);
        if (lane == 0) {
            g_bin_means[b] = (total > 0) ? (v / (double)total) : 0.0;
            __threadfence();                       // publish bin mean
            unsigned int t = atomicAdd(&g_ticket, 1u);
            s_last = (t == (unsigned int)(PSK * PSK - 1)) ? 1 : 0;
        }
    }
    __syncthreads();

    // Last-arriving block performs the final reduction (fixed order ->
    // deterministic) and resets the ticket for the next graph replay.
    if (s_last && wid == 0) {
        __threadfence();                           // acquire all bin means
        double v = (lane < PSK * PSK) ? g_bin_means[lane] : 0.0;
        if (lane + 32 < PSK * PSK) v += g_bin_means[lane + 32];
        v = warp_reduce_d(v);
        if (lane == 0) {
            out[0] = (float)(v / (double)(PSK * PSK));
            __threadfence();
            g_ticket = 0u;                         // reset for next replay
        }
    }
}

extern "C" void kernel_launch(void* const* d_in, const int* in_sizes, int n_in,
                              void* d_out, int out_size) {
    const float* x      = (const float*)d_in[0];  // (49, 1024, 1024) f32
    const float* region = (const float*)d_in[1];  // (4,) f32
    float* out = (float*)d_out;

    psroi_fused_kernel<<<PSK * PSK, 256>>>(x, region, out);
}

// round 13
// speedup vs baseline: 1.5638x; 1.2077x over previous
#include <cuda_runtime.h>
#include <cuda_bf16.h>
#include <math.h>

// PSROIPool (R-FCN), x: (49, 1024, 1024) f32, region: (4,) f32 ijhw.
// Output: scalar f32 = mean over 49 bins of per-bin spatial mean.
//
// R12 post-mortem: 49 blocks left 2/3 of the chip idle and each thread
// serialized ~31 latency-bound loads with a per-iteration integer divide.
// R13: 147 blocks (49 bins x 3 row-slices = one full wave, 1 block/SM),
// warp-per-row addressing (no div), fixed-slot partials + last-block
// deterministic reduction.

#define PSK     7
#define PSH     1024
#define PSW     1024
#define SLICES  3
#define NBLK    (PSK * PSK * SLICES)   // 147

__device__ double       g_partial[NBLK];
__device__ unsigned int g_ticket;      // zero-init; reset by last block each launch

__inline__ __device__ double warp_reduce_d(double v) {
#pragma unroll
    for (int o = 16; o > 0; o >>= 1)
        v += __shfl_down_sync(0xffffffffu, v, o);
    return v;
}

// per-bin integer extents from region (replicates reference fp32 math)
__device__ __forceinline__ void bin_extent(int bi, int bj,
                                           float ri, float rj, float rh, float rw,
                                           int& r0, int& r1, int& c0, int& c1) {
    const float i0 = ri - rh * 0.5f, i1 = ri + rh * 0.5f;
    const float j0 = rj - rw * 0.5f, j1 = rj + rw * 0.5f;
    const float ic = i0 + (i1 - i0) * ((float)(bi + 1) / (float)(PSK + 1));
    const float jc = j0 + (j1 - j0) * ((float)(bj + 1) / (float)(PSK + 1));
    const float bh = rh / (float)PSK;
    const float bw = rw / (float)PSK;
    r0 = max((int)floorf((ic - bh * 0.5f) * (float)PSH), 0);
    r1 = min((int)ceilf ((ic + bh * 0.5f) * (float)PSH), PSH);
    c0 = max((int)floorf((jc - bw * 0.5f) * (float)PSW), 0);
    c1 = min((int)ceilf ((jc + bw * 0.5f) * (float)PSW), PSW);
}

__global__ void __launch_bounds__(256)
psroi_fused_kernel(const float* __restrict__ x, const float* __restrict__ region,
                   float* __restrict__ out) {
    const int blk   = blockIdx.x;          // 0..146
    const int b     = blk / SLICES;        // bin 0..48
    const int slice = blk - b * SLICES;    // 0..2
    const int bi    = b / PSK;
    const int bj    = b % PSK;

    const float ri = region[0], rj = region[1], rh = region[2], rw = region[3];
    int r0, r1, c0, c1;
    bin_extent(bi, bj, ri, rj, rh, rw, r0, r1, c0, c1);

    const int nr       = r1 - r0;
    const int rows_per = (nr + SLICES - 1) / SLICES;
    const int rs       = r0 + slice * rows_per;
    const int re       = min(rs + rows_per, r1);

    const float* __restrict__ ch = x + (size_t)b * (PSH * PSW);

    const int lane = threadIdx.x & 31;
    const int wid  = threadIdx.x >> 5;

    // warp w handles rows rs+w, rs+w+8, ...; lanes stride 32 over [c0, c1)
    float facc = 0.0f;
    for (int r = rs + wid; r < re; r += 8) {
        const float* __restrict__ rowp = ch + (size_t)r * PSW;
#pragma unroll 4
        for (int c = c0 + lane; c < c1; c += 32)
            facc += __ldg(&rowp[c]);
    }

    __shared__ double wsum[8];
    double acc = warp_reduce_d((double)facc);
    if (lane == 0) wsum[wid] = acc;
    __syncthreads();

    __shared__ int s_last;
    if (wid == 0) {
        double v = (lane < 8) ? wsum[lane] : 0.0;
        v = warp_reduce_d(v);
        if (lane == 0) {
            g_partial[blk] = v;                    // raw slice sum, fixed slot
            __threadfence();
            unsigned int t = atomicAdd(&g_ticket, 1u);
            s_last = (t == (unsigned int)(NBLK - 1)) ? 1 : 0;
        }
    }
    __syncthreads();

    // Last-arriving block: deterministic final reduction.
    if (s_last && wid == 0) {
        __threadfence();
        // lane l handles bins l and l+32 (l+32 < 49 for l < 17)
        double v = 0.0;
#pragma unroll
        for (int rep = 0; rep < 2; rep++) {
            const int bb = lane + rep * 32;
            if (bb < PSK * PSK) {
                double s = g_partial[bb * SLICES + 0]
                         + g_partial[bb * SLICES + 1]
                         + g_partial[bb * SLICES + 2];
                int br0, br1, bc0, bc1;
                bin_extent(bb / PSK, bb % PSK, ri, rj, rh, rw, br0, br1, bc0, bc1);
                const int cnt = (br1 - br0) * (bc1 - bc0);
                v += (cnt > 0) ? (s / (double)cnt) : 0.0;
            }
        }
        v = warp_reduce_d(v);
        if (lane == 0) {
            out[0] = (float)(v / (double)(PSK * PSK));
            __threadfence();
            g_ticket = 0u;                         // reset for next replay
        }
    }
}

extern "C" void kernel_launch(void* const* d_in, const int* in_sizes, int n_in,
                              void* d_out, int out_size) {
    const float* x      = (const float*)d_in[0];  // (49, 1024, 1024) f32
    const float* region = (const float*)d_in[1];  // (4,) f32
    float* out = (float*)d_out;

    psroi_fused_kernel<<<NBLK, 256>>>(x, region, out);
}